// round 12
// baseline (speedup 1.0000x reference)
#include <cuda_runtime.h>
#include <math.h>
#include <float.h>

#define B_   8
#define N_   4096
#define M_   1024
#define K_   32
#define CIN_ 64
#define CT_  64
#define C1_  64
#define C2_  128
#define G_   8

// ---------------- device scratch (no allocations allowed) ----------------
__device__ int    g_nidx[B_ * M_ * K_];
__device__ float  g_fT[B_ * N_ * CIN_];          // features transposed [b][n][c]
__device__ float  g_tT[B_ * N_ * CT_];           // temb transposed     [b][n][c]
__device__ float  g_z1[B_ * M_ * C1_ * K_];      // [b][m][c][k]  (67 MB)
__device__ float  g_z2[B_ * M_ * C2_ * K_];      // [b][m][c][k]  (134 MB)
__device__ double g_p1[B_ * G_ * 512 * 2];       // per-block GN1 partials
__device__ double g_p2[B_ * G_ * 256 * 2];       // per-block GN2 partials
__device__ float  g_ms1[B_ * G_ * 2];
__device__ float  g_ms2[B_ * G_ * 2];

// ---------------- packed f32x2 helpers (2x FP32 FMA rate) ----------------
__device__ __forceinline__ unsigned long long ffma2(unsigned long long a,
                                                    unsigned long long b,
                                                    unsigned long long c) {
    unsigned long long d;
    asm("fma.rn.f32x2 %0, %1, %2, %3;" : "=l"(d) : "l"(a), "l"(b), "l"(c));
    return d;
}
__device__ __forceinline__ float2 upk(unsigned long long v) {
    float2 r;
    asm("mov.b64 {%0, %1}, %2;" : "=f"(r.x), "=f"(r.y) : "l"(v));
    return r;
}

// ---------------------------------------------------------------------
// Transpose features/temb: [b][64][4096] -> [b][4096][64]
// ---------------------------------------------------------------------
__global__ void tr_kernel(const float* __restrict__ f,
                          const float* __restrict__ t) {
    __shared__ float tile[32][33];
    const int b = blockIdx.z & 7;
    const float* src = (blockIdx.z < 8) ? f : t;
    float* dst       = (blockIdx.z < 8) ? g_fT : g_tT;
    const int n0 = blockIdx.x * 32, c0 = blockIdx.y * 32;
    tile[threadIdx.y][threadIdx.x] =
        src[((size_t)b * 64 + c0 + threadIdx.y) * N_ + n0 + threadIdx.x];
    __syncthreads();
    dst[((size_t)b * N_ + n0 + threadIdx.y) * 64 + c0 + threadIdx.x] =
        tile[threadIdx.x][threadIdx.y];
}

// ---------------------------------------------------------------------
// FPS: one block/batch, 1024 threads, 4 pts/thread in registers.
// One __syncthreads per iteration (parity double buffer); the winner
// lane publishes the far point's COORDS from registers -> no dependent
// global load. All warps redundantly do the final cross-warp reduce.
// Tie-breaking == jnp.argmax (first max): lane order == index order,
// warp order == index-block order; dist >= 0 so float bits are monotone.
// ---------------------------------------------------------------------
__global__ void fps_kernel(const float* __restrict__ coords,
                           float* __restrict__ centers) {
    const int b = blockIdx.x;
    const float* cx = coords + (b * 3 + 0) * N_;
    const float* cy = coords + (b * 3 + 1) * N_;
    const float* cz = coords + (b * 3 + 2) * N_;
    const int t = threadIdx.x, lane = t & 31, wid = t >> 5;
    const int n0 = t * 4;

    float4 vx = *(const float4*)(cx + n0);
    float4 vy = *(const float4*)(cy + n0);
    float4 vz = *(const float4*)(cz + n0);
    float px[4] = {vx.x, vx.y, vx.z, vx.w};
    float py[4] = {vy.x, vy.y, vy.z, vy.w};
    float pz[4] = {vz.x, vz.y, vz.z, vz.w};

    float fx = cx[0], fy = cy[0], fz = cz[0];
    float dist[4];
#pragma unroll
    for (int j = 0; j < 4; j++) {
        float dx = __fsub_rn(px[j], fx);
        float dy = __fsub_rn(py[j], fy);
        float dz = __fsub_rn(pz[j], fz);
        dist[j] = fmaf(dz, dz, fmaf(dy, dy, __fmul_rn(dx, dx)));
    }
    if (t == 0) {
        centers[(b * 3 + 0) * M_] = fx;
        centers[(b * 3 + 1) * M_] = fy;
        centers[(b * 3 + 2) * M_] = fz;
    }

    __shared__ unsigned swk[2][32];
    __shared__ float    swx[2][32], swy[2][32], swz[2][32];
    int p = 0;

    for (int s = 1; s < M_; s++) {
        // local argmax over 4 (strict > keeps lowest index), track coords
        float bd = dist[0], bx = px[0], by = py[0], bz = pz[0];
#pragma unroll
        for (int j = 1; j < 4; j++)
            if (dist[j] > bd) { bd = dist[j]; bx = px[j]; by = py[j]; bz = pz[j]; }

        unsigned key  = __float_as_uint(bd);
        unsigned wmax = __reduce_max_sync(0xffffffffu, key);
        unsigned msk  = __ballot_sync(0xffffffffu, key == wmax);
        if (lane == __ffs(msk) - 1) {
            swk[p][wid] = wmax;
            swx[p][wid] = bx; swy[p][wid] = by; swz[p][wid] = bz;
        }
        __syncthreads();

        // every warp redundantly reduces the 32 warp entries
        unsigned k2  = swk[p][lane];
        unsigned m2  = __reduce_max_sync(0xffffffffu, k2);
        unsigned mk2 = __ballot_sync(0xffffffffu, k2 == m2);
        int sw = __ffs(mk2) - 1;
        fx = swx[p][sw]; fy = swy[p][sw]; fz = swz[p][sw];
        if (t == 0) {
            centers[(b * 3 + 0) * M_ + s] = fx;
            centers[(b * 3 + 1) * M_ + s] = fy;
            centers[(b * 3 + 2) * M_ + s] = fz;
        }
#pragma unroll
        for (int j = 0; j < 4; j++) {
            float dx = __fsub_rn(px[j], fx);
            float dy = __fsub_rn(py[j], fy);
            float dz = __fsub_rn(pz[j], fz);
            dist[j] = fminf(dist[j], fmaf(dz, dz, fmaf(dy, dy, __fmul_rn(dx, dx))));
        }
        p ^= 1;
    }
}

// ---------------------------------------------------------------------
// kNN (unchanged from passing version).
// ---------------------------------------------------------------------
__global__ void knn_kernel(const float* __restrict__ coords,
                           const float* __restrict__ centers) {
    const int m = blockIdx.x, b = blockIdx.y, tid = threadIdx.x;
    __shared__ unsigned long long skey[N_];
    __shared__ unsigned long long scur[256];
    __shared__ unsigned long long s_win;

    const float* cx = coords + (b * 3 + 0) * N_;
    const float* cy = coords + (b * 3 + 1) * N_;
    const float* cz = coords + (b * 3 + 2) * N_;
    const float qx = centers[(b * 3 + 0) * M_ + m];
    const float qy = centers[(b * 3 + 1) * M_ + m];
    const float qz = centers[(b * 3 + 2) * M_ + m];
    const float cn = fmaf(qz, qz, fmaf(qy, qy, __fmul_rn(qx, qx)));

    for (int n = tid; n < N_; n += 256) {
        float x = cx[n], y = cy[n], z = cz[n];
        float pn = fmaf(z, z, fmaf(y, y, __fmul_rn(x, x)));
        float dt = fmaf(qz, z, fmaf(qy, y, __fmul_rn(qx, x)));
        float d  = __fsub_rn(__fadd_rn(cn, pn), __fmul_rn(2.0f, dt));
        unsigned ub = __float_as_uint(d);
        ub = (ub & 0x80000000u) ? ~ub : (ub | 0x80000000u);
        skey[n] = ((unsigned long long)ub << 32) | (unsigned)n;
    }
    {
        unsigned long long best = ~0ull;
#pragma unroll
        for (int j = 0; j < N_ / 256; j++) {
            unsigned long long v = skey[tid + j * 256];
            best = (v < best) ? v : best;
        }
        scur[tid] = best;
    }
    __syncthreads();

    int* outp = g_nidx + (b * M_ + m) * K_;
    for (int r = 0; r < K_; r++) {
        if (tid < 32) {
            unsigned long long mk = scur[tid];
#pragma unroll
            for (int j = 1; j < 8; j++) {
                unsigned long long v = scur[tid + j * 32];
                mk = (v < mk) ? v : mk;
            }
#pragma unroll
            for (int off = 16; off > 0; off >>= 1) {
                unsigned long long v = __shfl_down_sync(0xffffffffu, mk, off);
                mk = (v < mk) ? v : mk;
            }
            if (tid == 0) { s_win = mk; outp[r] = (int)(unsigned)mk; }
        }
        __syncthreads();
        unsigned long long wk = s_win;
        if (scur[tid] == wk) {
            unsigned long long best = ~0ull;
#pragma unroll
            for (int j = 0; j < N_ / 256; j++) {
                int pos = tid + j * 256;
                unsigned long long v = skey[pos];
                if (v == wk) { skey[pos] = ~0ull; v = ~0ull; }
                best = (v < best) ? v : best;
            }
            scur[tid] = best;
        }
        __syncthreads();
    }
}

// ---------------------------------------------------------------------
// MLP1: gather via transposed tensors, z1 = W1*gfeat + b1 (f32x2 GEMM),
// fused GN1 partial stats (warp og == group og), gtemb max.
// Block: 2 m's, 256 threads. z1 layout [b][m][c][k].
// ---------------------------------------------------------------------
__global__ __launch_bounds__(256) void mlp1_kernel(
        const float* __restrict__ coords,
        const float* __restrict__ W1,
        const float* __restrict__ b1,
        const float* __restrict__ centers,
        float* __restrict__ out_temb) {
    const int b = blockIdx.y, m0 = blockIdx.x * 2, tid = threadIdx.x;
    __shared__ __align__(16) float sW[C1_ * 68];
    __shared__ __align__(16) float sF[2][K_ * 68];
    __shared__ int sN[2][K_];

    for (int i = tid; i < C1_ * 68; i += 256) {
        int o = i / 68, c = i - o * 68;
        sW[i] = (c < 67) ? W1[o * 67 + c] : 0.0f;
    }
    if (tid < 64) {
        int mt = tid >> 5, kk = tid & 31;
        sN[mt][kk] = g_nidx[(b * M_ + m0 + mt) * K_ + kk];
    }
    __syncthreads();

    // fill sF: rel-coords (c 0..2), features (c 3..66), pad (c 67)
    for (int i = tid; i < 2 * 2048; i += 256) {
        int mt = i >> 11, r = i & 2047, kk = r >> 6, c = r & 63;
        sF[mt][kk * 68 + 3 + c] = g_fT[((size_t)b * N_ + sN[mt][kk]) * 64 + c];
    }
    {
        int mt = tid >> 7, r = tid & 127, kk = r >> 2, d = r & 3;
        if (d < 3) {
            float ctr = centers[(b * 3 + d) * M_ + m0 + mt];
            sF[mt][kk * 68 + d] =
                __fsub_rn(coords[(b * 3 + d) * N_ + sN[mt][kk]], ctr);
        }
    }
    if (tid < 64) sF[tid >> 5][(tid & 31) * 68 + 67] = 0.0f;

    // gtemb max over K (transposed temb: coalesced over c)
    if (tid < 128) {
        int mt = tid >> 6, c = tid & 63;
        float mx = -FLT_MAX;
#pragma unroll
        for (int kk = 0; kk < K_; kk++)
            mx = fmaxf(mx, g_tT[((size_t)b * N_ + sN[mt][kk]) * 64 + c]);
        out_temb[(b * CT_ + c) * M_ + m0 + mt] = mx;
    }
    __syncthreads();

    const int k = tid & 31, og = tid >> 5, ob = og * 8;  // group == og
    double ds = 0.0, dsq = 0.0;
    for (int mt = 0; mt < 2; mt++) {
        const float* fb = &sF[mt][0];
        unsigned long long alo[8], ahi[8];
#pragma unroll
        for (int o = 0; o < 8; o++) { alo[o] = 0ull; ahi[o] = 0ull; }
#pragma unroll
        for (int cs = 0; cs < 17; cs++) {
            const int c = cs * 4;
            ulonglong2 f = *reinterpret_cast<const ulonglong2*>(&fb[k * 68 + c]);
#pragma unroll
            for (int o = 0; o < 8; o++) {
                ulonglong2 w = *reinterpret_cast<const ulonglong2*>(&sW[(ob + o) * 68 + c]);
                alo[o] = ffma2(w.x, f.x, alo[o]);
                ahi[o] = ffma2(w.y, f.y, ahi[o]);
            }
        }
        float* zp = g_z1 + (((size_t)(b * M_ + m0 + mt)) * C1_ + ob) * K_ + k;
#pragma unroll
        for (int o = 0; o < 8; o++) {
            float2 lo = upk(alo[o]), hi = upk(ahi[o]);
            float s = b1[ob + o] + ((lo.x + lo.y) + (hi.x + hi.y));
            zp[o * K_] = s;
            ds  += (double)s;
            dsq += (double)s * (double)s;
        }
    }
#pragma unroll
    for (int off = 16; off > 0; off >>= 1) {
        ds  += __shfl_down_sync(0xffffffffu, ds,  off);
        dsq += __shfl_down_sync(0xffffffffu, dsq, off);
    }
    if (k == 0) {
        size_t slot = ((size_t)(b * G_ + og) * 512 + blockIdx.x) * 2;
        g_p1[slot] = ds; g_p1[slot + 1] = dsq;
    }
}

// ---------------------------------------------------------------------
// GN finalize (both phases). 512 threads: 8 lanes per group, fp64.
// ---------------------------------------------------------------------
template <int PHASE>
__global__ void gn_fin_kernel() {
    const int    tiles = PHASE ? 256 : 512;
    const double cnt   = PHASE ? 524288.0 : 262144.0;
    const double* part = PHASE ? g_p2 : g_p1;
    float* ms          = PHASE ? g_ms2 : g_ms1;
    const int g = threadIdx.x >> 3, j = threadIdx.x & 7;
    double s = 0.0, sq = 0.0;
    for (int i = j; i < tiles; i += 8) {
        s  += part[((size_t)g * tiles + i) * 2];
        sq += part[((size_t)g * tiles + i) * 2 + 1];
    }
#pragma unroll
    for (int off = 4; off > 0; off >>= 1) {
        s  += __shfl_down_sync(0xffffffffu, s,  off);
        sq += __shfl_down_sync(0xffffffffu, sq, off);
    }
    if (j == 0) {
        double mean = s / cnt;
        double var  = sq / cnt - mean * mean;
        if (var < 0.0) var = 0.0;
        ms[g * 2]     = (float)mean;
        ms[g * 2 + 1] = (float)rsqrt(var + 1e-5);
    }
}

// ---------------------------------------------------------------------
// MLP2: normalize+swish(z1) -> z2 = W2*h + b2 (f32x2 GEMM),
// fused GN2 partial stats (warp og == group og). Block: 4 m's.
// ---------------------------------------------------------------------
__global__ __launch_bounds__(256) void mlp2_kernel(
        const float* __restrict__ W2,
        const float* __restrict__ b2,
        const float* __restrict__ g1,
        const float* __restrict__ be1) {
    const int b = blockIdx.y, m0 = blockIdx.x * 4, tid = threadIdx.x;
    __shared__ __align__(16) float sW[C2_ * C1_];   // 32 KB
    __shared__ __align__(16) float sH[K_ * 68];     // 8.7 KB
    __shared__ float sG[64], sB[64], sMs[16], sB2[128];

    for (int i = tid; i < C2_ * C1_; i += 256) sW[i] = W2[i];
    if (tid < 64)  { sG[tid] = g1[tid]; sB[tid] = be1[tid]; }
    if (tid < 16)  sMs[tid] = g_ms1[b * 16 + tid];
    if (tid < 128) sB2[tid] = b2[tid];

    const int k = tid & 31, og = tid >> 5, ob = og * 16;  // group == og
    double ds = 0.0, dsq = 0.0;

    for (int mt = 0; mt < 4; mt++) {
        const int m = m0 + mt;
        __syncthreads();    // previous GEMM done (and phase-0 loads on mt=0)
        const float4* zin = (const float4*)(g_z1 + (size_t)(b * M_ + m) * 2048);
#pragma unroll
        for (int j = 0; j < 2; j++) {
            int e4 = tid + j * 256;
            float4 v = zin[e4];
            int e = e4 * 4, c = e >> 5, kk = e & 31;
            float mean = sMs[(c >> 3) * 2], rstd = sMs[(c >> 3) * 2 + 1];
            float gg = sG[c], bb = sB[c];
            float vv[4] = {v.x, v.y, v.z, v.w};
#pragma unroll
            for (int q = 0; q < 4; q++) {
                float t = fmaf(__fmul_rn(__fsub_rn(vv[q], mean), rstd), gg, bb);
                float sg = 1.0f / (1.0f + expf(-t));
                sH[(kk + q) * 68 + c] = t * sg;
            }
        }
        __syncthreads();

        unsigned long long alo[16], ahi[16];
#pragma unroll
        for (int o = 0; o < 16; o++) { alo[o] = 0ull; ahi[o] = 0ull; }
#pragma unroll
        for (int cs = 0; cs < 16; cs++) {
            const int c = cs * 4;
            ulonglong2 f = *reinterpret_cast<const ulonglong2*>(&sH[k * 68 + c]);
#pragma unroll
            for (int o = 0; o < 16; o++) {
                ulonglong2 w = *reinterpret_cast<const ulonglong2*>(&sW[(ob + o) * 64 + c]);
                alo[o] = ffma2(w.x, f.x, alo[o]);
                ahi[o] = ffma2(w.y, f.y, ahi[o]);
            }
        }
        float* zp = g_z2 + (((size_t)(b * M_ + m)) * C2_ + ob) * K_ + k;
#pragma unroll
        for (int o = 0; o < 16; o++) {
            float2 lo = upk(alo[o]), hi = upk(ahi[o]);
            float s = sB2[ob + o] + ((lo.x + lo.y) + (hi.x + hi.y));
            zp[o * K_] = s;
            ds  += (double)s;
            dsq += (double)s * (double)s;
        }
    }
#pragma unroll
    for (int off = 16; off > 0; off >>= 1) {
        ds  += __shfl_down_sync(0xffffffffu, ds,  off);
        dsq += __shfl_down_sync(0xffffffffu, dsq, off);
    }
    if (k == 0) {
        size_t slot = ((size_t)(b * G_ + og) * 256 + blockIdx.x) * 2;
        g_p2[slot] = ds; g_p2[slot + 1] = dsq;
    }
}

// ---------------------------------------------------------------------
// Out: normalize+swish(z2), max over K. z2 layout [b][m][c][k].
// out index = (b*C2 + c)*M + m.
// ---------------------------------------------------------------------
__global__ void out_kernel(const float* __restrict__ g2,
                           const float* __restrict__ be2,
                           float* __restrict__ out) {
    const int idx = blockIdx.x * 256 + threadIdx.x;
    const int b = idx >> 17, c = (idx >> 10) & (C2_ - 1), m = idx & (M_ - 1);
    const float mean = g_ms2[(b * G_ + (c >> 4)) * 2];
    const float rstd = g_ms2[(b * G_ + (c >> 4)) * 2 + 1];
    const float gam = g2[c], bet = be2[c];
    const float4* p = (const float4*)(g_z2 + ((size_t)(b * M_ + m) * C2_ + c) * K_);
    float mx = -FLT_MAX;
#pragma unroll
    for (int j = 0; j < K_ / 4; j++) {
        float4 v = p[j];
        float vv[4] = {v.x, v.y, v.z, v.w};
#pragma unroll
        for (int q = 0; q < 4; q++) {
            float t = fmaf(__fmul_rn(__fsub_rn(vv[q], mean), rstd), gam, bet);
            float s = t / (1.0f + expf(-t));
            mx = fmaxf(mx, s);
        }
    }
    out[idx] = mx;
}

// ---------------------------------------------------------------------
extern "C" void kernel_launch(void* const* d_in, const int* in_sizes, int n_in,
                              void* d_out, int out_size) {
    const float* features = (const float*)d_in[0];
    const float* coords   = (const float*)d_in[1];
    const float* temb     = (const float*)d_in[2];
    const float* W1  = (const float*)d_in[3];
    const float* b1  = (const float*)d_in[4];
    const float* g1  = (const float*)d_in[5];
    const float* be1 = (const float*)d_in[6];
    const float* W2  = (const float*)d_in[7];
    const float* b2  = (const float*)d_in[8];
    const float* g2  = (const float*)d_in[9];
    const float* be2 = (const float*)d_in[10];

    float* out      = (float*)d_out;
    float* out_h    = out;                    // [B, C2, M]
    float* out_ctr  = out + B_ * C2_ * M_;    // [B, 3, M]
    float* out_temb = out_ctr + B_ * 3 * M_;  // [B, CT, M]

    tr_kernel<<<dim3(N_ / 32, 2, 16), dim3(32, 32)>>>(features, temb);
    fps_kernel<<<B_, 1024>>>(coords, out_ctr);
    knn_kernel<<<dim3(M_, B_), 256>>>(coords, out_ctr);
    mlp1_kernel<<<dim3(M_ / 2, B_), 256>>>(coords, W1, b1, out_ctr, out_temb);
    gn_fin_kernel<0><<<1, 512>>>();
    mlp2_kernel<<<dim3(M_ / 4, B_), 256>>>(W2, b2, g1, be1);
    gn_fin_kernel<1><<<1, 512>>>();
    out_kernel<<<(B_ * C2_ * M_) / 256, 256>>>(g2, be2, out_h);
}

// round 13
// speedup vs baseline: 1.6438x; 1.6438x over previous
#include <cuda_runtime.h>
#include <math.h>
#include <float.h>

#define B_   8
#define N_   4096
#define M_   1024
#define K_   32
#define CIN_ 64
#define CT_  64
#define C1_  64
#define C2_  128
#define G_   8

// ---------------- device scratch (no allocations allowed) ----------------
__device__ int    g_nidx[B_ * M_ * K_];
__device__ float  g_fT[B_ * N_ * CIN_];          // features transposed [b][n][c]
__device__ float  g_tT[B_ * N_ * CT_];           // temb transposed     [b][n][c]
__device__ float  g_z1[B_ * C1_ * M_ * K_];      // [b][c][m][k]  (67 MB)
__device__ float  g_z2[B_ * C2_ * M_ * K_];      // [b][c][m][k]  (134 MB)
__device__ double g_p1[B_ * G_ * 512 * 2];       // per-block GN1 partials
__device__ double g_p2[B_ * G_ * 256 * 2];       // per-block GN2 partials
__device__ float  g_ms1[B_ * G_ * 2];
__device__ float  g_ms2[B_ * G_ * 2];

// ---------------------------------------------------------------------
// Transpose features/temb: [b][64][4096] -> [b][4096][64]
// ---------------------------------------------------------------------
__global__ void tr_kernel(const float* __restrict__ f,
                          const float* __restrict__ t) {
    __shared__ float tile[32][33];
    const int b = blockIdx.z & 7;
    const float* src = (blockIdx.z < 8) ? f : t;
    float* dst       = (blockIdx.z < 8) ? g_fT : g_tT;
    const int n0 = blockIdx.x * 32, c0 = blockIdx.y * 32;
    tile[threadIdx.y][threadIdx.x] =
        src[((size_t)b * 64 + c0 + threadIdx.y) * N_ + n0 + threadIdx.x];
    __syncthreads();
    dst[((size_t)b * N_ + n0 + threadIdx.y) * 64 + c0 + threadIdx.x] =
        tile[threadIdx.x][threadIdx.y];
}

// ---------------------------------------------------------------------
// FPS: one block/batch, 1024 threads, 4 pts/thread in registers.
// One __syncthreads per iteration (parity double buffer); the winner
// lane publishes the far point's COORDS from registers. Tie-breaking
// matches jnp.argmax (first max = lowest index).
// ---------------------------------------------------------------------
__global__ void fps_kernel(const float* __restrict__ coords,
                           float* __restrict__ centers) {
    const int b = blockIdx.x;
    const float* cx = coords + (b * 3 + 0) * N_;
    const float* cy = coords + (b * 3 + 1) * N_;
    const float* cz = coords + (b * 3 + 2) * N_;
    const int t = threadIdx.x, lane = t & 31, wid = t >> 5;
    const int n0 = t * 4;

    float4 vx = *(const float4*)(cx + n0);
    float4 vy = *(const float4*)(cy + n0);
    float4 vz = *(const float4*)(cz + n0);
    float px[4] = {vx.x, vx.y, vx.z, vx.w};
    float py[4] = {vy.x, vy.y, vy.z, vy.w};
    float pz[4] = {vz.x, vz.y, vz.z, vz.w};

    float fx = cx[0], fy = cy[0], fz = cz[0];
    float dist[4];
#pragma unroll
    for (int j = 0; j < 4; j++) {
        float dx = __fsub_rn(px[j], fx);
        float dy = __fsub_rn(py[j], fy);
        float dz = __fsub_rn(pz[j], fz);
        dist[j] = fmaf(dz, dz, fmaf(dy, dy, __fmul_rn(dx, dx)));
    }
    if (t == 0) {
        centers[(b * 3 + 0) * M_] = fx;
        centers[(b * 3 + 1) * M_] = fy;
        centers[(b * 3 + 2) * M_] = fz;
    }

    __shared__ unsigned swk[2][32];
    __shared__ float    swx[2][32], swy[2][32], swz[2][32];
    int p = 0;

    for (int s = 1; s < M_; s++) {
        float bd = dist[0], bx = px[0], by = py[0], bz = pz[0];
#pragma unroll
        for (int j = 1; j < 4; j++)
            if (dist[j] > bd) { bd = dist[j]; bx = px[j]; by = py[j]; bz = pz[j]; }

        unsigned key  = __float_as_uint(bd);
        unsigned wmax = __reduce_max_sync(0xffffffffu, key);
        unsigned msk  = __ballot_sync(0xffffffffu, key == wmax);
        if (lane == __ffs(msk) - 1) {
            swk[p][wid] = wmax;
            swx[p][wid] = bx; swy[p][wid] = by; swz[p][wid] = bz;
        }
        __syncthreads();

        unsigned k2  = swk[p][lane];
        unsigned m2  = __reduce_max_sync(0xffffffffu, k2);
        unsigned mk2 = __ballot_sync(0xffffffffu, k2 == m2);
        int sw = __ffs(mk2) - 1;
        fx = swx[p][sw]; fy = swy[p][sw]; fz = swz[p][sw];
        if (t == 0) {
            centers[(b * 3 + 0) * M_ + s] = fx;
            centers[(b * 3 + 1) * M_ + s] = fy;
            centers[(b * 3 + 2) * M_ + s] = fz;
        }
#pragma unroll
        for (int j = 0; j < 4; j++) {
            float dx = __fsub_rn(px[j], fx);
            float dy = __fsub_rn(py[j], fy);
            float dz = __fsub_rn(pz[j], fz);
            dist[j] = fminf(dist[j], fmaf(dz, dz, fmaf(dy, dy, __fmul_rn(dx, dx))));
        }
        p ^= 1;
    }
}

// ---------------------------------------------------------------------
// kNN (unchanged from passing version).
// ---------------------------------------------------------------------
__global__ void knn_kernel(const float* __restrict__ coords,
                           const float* __restrict__ centers) {
    const int m = blockIdx.x, b = blockIdx.y, tid = threadIdx.x;
    __shared__ unsigned long long skey[N_];
    __shared__ unsigned long long scur[256];
    __shared__ unsigned long long s_win;

    const float* cx = coords + (b * 3 + 0) * N_;
    const float* cy = coords + (b * 3 + 1) * N_;
    const float* cz = coords + (b * 3 + 2) * N_;
    const float qx = centers[(b * 3 + 0) * M_ + m];
    const float qy = centers[(b * 3 + 1) * M_ + m];
    const float qz = centers[(b * 3 + 2) * M_ + m];
    const float cn = fmaf(qz, qz, fmaf(qy, qy, __fmul_rn(qx, qx)));

    for (int n = tid; n < N_; n += 256) {
        float x = cx[n], y = cy[n], z = cz[n];
        float pn = fmaf(z, z, fmaf(y, y, __fmul_rn(x, x)));
        float dt = fmaf(qz, z, fmaf(qy, y, __fmul_rn(qx, x)));
        float d  = __fsub_rn(__fadd_rn(cn, pn), __fmul_rn(2.0f, dt));
        unsigned ub = __float_as_uint(d);
        ub = (ub & 0x80000000u) ? ~ub : (ub | 0x80000000u);
        skey[n] = ((unsigned long long)ub << 32) | (unsigned)n;
    }
    {
        unsigned long long best = ~0ull;
#pragma unroll
        for (int j = 0; j < N_ / 256; j++) {
            unsigned long long v = skey[tid + j * 256];
            best = (v < best) ? v : best;
        }
        scur[tid] = best;
    }
    __syncthreads();

    int* outp = g_nidx + (b * M_ + m) * K_;
    for (int r = 0; r < K_; r++) {
        if (tid < 32) {
            unsigned long long mk = scur[tid];
#pragma unroll
            for (int j = 1; j < 8; j++) {
                unsigned long long v = scur[tid + j * 32];
                mk = (v < mk) ? v : mk;
            }
#pragma unroll
            for (int off = 16; off > 0; off >>= 1) {
                unsigned long long v = __shfl_down_sync(0xffffffffu, mk, off);
                mk = (v < mk) ? v : mk;
            }
            if (tid == 0) { s_win = mk; outp[r] = (int)(unsigned)mk; }
        }
        __syncthreads();
        unsigned long long wk = s_win;
        if (scur[tid] == wk) {
            unsigned long long best = ~0ull;
#pragma unroll
            for (int j = 0; j < N_ / 256; j++) {
                int pos = tid + j * 256;
                unsigned long long v = skey[pos];
                if (v == wk) { skey[pos] = ~0ull; v = ~0ull; }
                best = (v < best) ? v : best;
            }
            scur[tid] = best;
        }
        __syncthreads();
    }
}

// ---------------------------------------------------------------------
// MLP1: transposed gather -> z1 = W1*gfeat + b1 (scalar GEMM, 2-m
// register blocking), fused GN1 partials (warp og == group), gtemb max.
// z1 layout [b][c][m][k]. Block: 2 m's, 256 threads, ~34.4 KB smem.
// ---------------------------------------------------------------------
__global__ __launch_bounds__(256) void mlp1_kernel(
        const float* __restrict__ coords,
        const float* __restrict__ W1,
        const float* __restrict__ b1,
        const float* __restrict__ centers,
        float* __restrict__ out_temb) {
    const int b = blockIdx.y, m0 = blockIdx.x * 2, tid = threadIdx.x;
    __shared__ float sW[C1_ * 67];       // 17.15 KB
    __shared__ float sF[2][K_ * 67];     // 17.15 KB, stride 67 (odd-ish: conflict-free)
    __shared__ int   sN[2][K_];

    for (int i = tid; i < C1_ * 67; i += 256) sW[i] = W1[i];
    if (tid < 64) {
        int mt = tid >> 5, kk = tid & 31;
        sN[mt][kk] = g_nidx[(b * M_ + m0 + mt) * K_ + kk];
    }
    __syncthreads();

    // features: contiguous 256 B per neighbor row from g_fT
    for (int i = tid; i < 2 * 2048; i += 256) {
        int mt = i >> 11, r = i & 2047, kk = r >> 6, c = r & 63;
        sF[mt][kk * 67 + 3 + c] = g_fT[((size_t)b * N_ + sN[mt][kk]) * 64 + c];
    }
    // rel-coords
    {
        int mt = tid >> 7, r = tid & 127, kk = r >> 2, d = r & 3;
        if (d < 3) {
            float ctr = centers[(b * 3 + d) * M_ + m0 + mt];
            sF[mt][kk * 67 + d] =
                __fsub_rn(coords[(b * 3 + d) * N_ + sN[mt][kk]], ctr);
        }
    }
    // gtemb max over K (coalesced over c in transposed temb)
    if (tid < 128) {
        int mt = tid >> 6, c = tid & 63;
        float mx = -FLT_MAX;
#pragma unroll
        for (int kk = 0; kk < K_; kk++)
            mx = fmaxf(mx, g_tT[((size_t)b * N_ + sN[mt][kk]) * 64 + c]);
        out_temb[(b * CT_ + c) * M_ + m0 + mt] = mx;
    }
    __syncthreads();

    const int k = tid & 31, og = tid >> 5, ob = og * 8;   // group == og
    float a0[8], a1[8];
#pragma unroll
    for (int o = 0; o < 8; o++) { a0[o] = b1[ob + o]; a1[o] = a0[o]; }
    for (int c = 0; c < 67; c++) {
        float f0 = sF[0][k * 67 + c];
        float f1 = sF[1][k * 67 + c];
#pragma unroll
        for (int o = 0; o < 8; o++) {
            float w = sW[(ob + o) * 67 + c];
            a0[o] = fmaf(w, f0, a0[o]);
            a1[o] = fmaf(w, f1, a1[o]);
        }
    }
    double ds = 0.0, dsq = 0.0;
#pragma unroll
    for (int o = 0; o < 8; o++) {
        g_z1[((size_t)(b * C1_ + ob + o) * M_ + m0 + 0) * K_ + k] = a0[o];
        g_z1[((size_t)(b * C1_ + ob + o) * M_ + m0 + 1) * K_ + k] = a1[o];
        ds  += (double)a0[o] + (double)a1[o];
        dsq += (double)a0[o] * (double)a0[o] + (double)a1[o] * (double)a1[o];
    }
#pragma unroll
    for (int off = 16; off > 0; off >>= 1) {
        ds  += __shfl_down_sync(0xffffffffu, ds,  off);
        dsq += __shfl_down_sync(0xffffffffu, dsq, off);
    }
    if (k == 0) {
        size_t slot = ((size_t)(b * G_ + og) * 512 + blockIdx.x) * 2;
        g_p1[slot] = ds; g_p1[slot + 1] = dsq;
    }
}

// ---------------------------------------------------------------------
// GN finalize (both phases), fp64.
// ---------------------------------------------------------------------
template <int PHASE>
__global__ void gn_fin_kernel() {
    const int    tiles = PHASE ? 256 : 512;
    const double cnt   = PHASE ? 524288.0 : 262144.0;
    const double* part = PHASE ? g_p2 : g_p1;
    float* ms          = PHASE ? g_ms2 : g_ms1;
    const int g = threadIdx.x >> 3, j = threadIdx.x & 7;
    double s = 0.0, sq = 0.0;
    for (int i = j; i < tiles; i += 8) {
        s  += part[((size_t)g * tiles + i) * 2];
        sq += part[((size_t)g * tiles + i) * 2 + 1];
    }
#pragma unroll
    for (int off = 4; off > 0; off >>= 1) {
        s  += __shfl_down_sync(0xffffffffu, s,  off);
        sq += __shfl_down_sync(0xffffffffu, sq, off);
    }
    if (j == 0) {
        double mean = s / cnt;
        double var  = sq / cnt - mean * mean;
        if (var < 0.0) var = 0.0;
        ms[g * 2]     = (float)mean;
        ms[g * 2 + 1] = (float)rsqrt(var + 1e-5);
    }
}

// ---------------------------------------------------------------------
// MLP2: normalize+swish(z1) -> z2 = W2*h + b2 (scalar GEMM, 2-m register
// blocking, 2 pairs per block), fused GN2 partials.
// sH layout [c][k] (stride 32): conflict-free fill AND read.
// Block: 4 m's, 256 threads, exactly 48 KB smem.
// ---------------------------------------------------------------------
__global__ __launch_bounds__(256) void mlp2_kernel(
        const float* __restrict__ W2,
        const float* __restrict__ b2,
        const float* __restrict__ g1,
        const float* __restrict__ be1) {
    const int b = blockIdx.y, m0 = blockIdx.x * 4, tid = threadIdx.x;
    __shared__ float sW[C2_ * C1_];     // 32 KB
    __shared__ float sH[2][C1_ * K_];   // 16 KB
    for (int i = tid; i < C2_ * C1_; i += 256) sW[i] = W2[i];

    const int k = tid & 31, og = tid >> 5, ob = og * 16;  // group == og
    double ds = 0.0, dsq = 0.0;

    for (int pr = 0; pr < 2; pr++) {
        const int m = m0 + pr * 2;
        __syncthreads();   // sW ready (pr=0) / previous GEMM done (pr=1)
        for (int i = tid; i < 2 * C1_ * K_; i += 256) {
            int mt = i >> 11, r = i & 2047, c = r >> 5, kk = r & 31;
            float v = g_z1[((size_t)(b * C1_ + c) * M_ + m + mt) * K_ + kk];
            int g = c >> 3;
            float mean = g_ms1[(b * G_ + g) * 2];
            float rstd = g_ms1[(b * G_ + g) * 2 + 1];
            float t = fmaf(__fmul_rn(__fsub_rn(v, mean), rstd), g1[c], be1[c]);
            float sg = 1.0f / (1.0f + expf(-t));
            sH[mt][c * K_ + kk] = t * sg;
        }
        __syncthreads();

        float a0[16], a1[16];
#pragma unroll
        for (int o = 0; o < 16; o++) { a0[o] = b2[ob + o]; a1[o] = a0[o]; }
        for (int c = 0; c < C1_; c++) {
            float f0 = sH[0][c * K_ + k];
            float f1 = sH[1][c * K_ + k];
#pragma unroll
            for (int o = 0; o < 16; o++) {
                float w = sW[(ob + o) * C1_ + c];
                a0[o] = fmaf(w, f0, a0[o]);
                a1[o] = fmaf(w, f1, a1[o]);
            }
        }
#pragma unroll
        for (int o = 0; o < 16; o++) {
            g_z2[((size_t)(b * C2_ + ob + o) * M_ + m + 0) * K_ + k] = a0[o];
            g_z2[((size_t)(b * C2_ + ob + o) * M_ + m + 1) * K_ + k] = a1[o];
            ds  += (double)a0[o] + (double)a1[o];
            dsq += (double)a0[o] * (double)a0[o] + (double)a1[o] * (double)a1[o];
        }
    }
#pragma unroll
    for (int off = 16; off > 0; off >>= 1) {
        ds  += __shfl_down_sync(0xffffffffu, ds,  off);
        dsq += __shfl_down_sync(0xffffffffu, dsq, off);
    }
    if (k == 0) {
        size_t slot = ((size_t)(b * G_ + og) * 256 + blockIdx.x) * 2;
        g_p2[slot] = ds; g_p2[slot + 1] = dsq;
    }
}

// ---------------------------------------------------------------------
// Out: normalize+swish(z2), max over K. z2 layout [b][c][m][k].
// ---------------------------------------------------------------------
__global__ void out_kernel(const float* __restrict__ g2,
                           const float* __restrict__ be2,
                           float* __restrict__ out) {
    const int idx = blockIdx.x * 256 + threadIdx.x;   // (b, c, m)
    const int c = (idx >> 10) & (C2_ - 1);
    const int b = idx >> 17;
    const float mean = g_ms2[(b * G_ + (c >> 4)) * 2];
    const float rstd = g_ms2[(b * G_ + (c >> 4)) * 2 + 1];
    const float gam = g2[c], bet = be2[c];
    const float4* p = (const float4*)(g_z2 + (size_t)idx * K_);
    float mx = -FLT_MAX;
#pragma unroll
    for (int j = 0; j < K_ / 4; j++) {
        float4 v = p[j];
        float vv[4] = {v.x, v.y, v.z, v.w};
#pragma unroll
        for (int q = 0; q < 4; q++) {
            float t = fmaf(__fmul_rn(__fsub_rn(vv[q], mean), rstd), gam, bet);
            float s = t / (1.0f + expf(-t));
            mx = fmaxf(mx, s);
        }
    }
    out[idx] = mx;
}

// ---------------------------------------------------------------------
extern "C" void kernel_launch(void* const* d_in, const int* in_sizes, int n_in,
                              void* d_out, int out_size) {
    const float* features = (const float*)d_in[0];
    const float* coords   = (const float*)d_in[1];
    const float* temb     = (const float*)d_in[2];
    const float* W1  = (const float*)d_in[3];
    const float* b1  = (const float*)d_in[4];
    const float* g1  = (const float*)d_in[5];
    const float* be1 = (const float*)d_in[6];
    const float* W2  = (const float*)d_in[7];
    const float* b2  = (const float*)d_in[8];
    const float* g2  = (const float*)d_in[9];
    const float* be2 = (const float*)d_in[10];

    float* out      = (float*)d_out;
    float* out_h    = out;                    // [B, C2, M]
    float* out_ctr  = out + B_ * C2_ * M_;    // [B, 3, M]
    float* out_temb = out_ctr + B_ * 3 * M_;  // [B, CT, M]

    tr_kernel<<<dim3(N_ / 32, 2, 16), dim3(32, 32)>>>(features, temb);
    fps_kernel<<<B_, 1024>>>(coords, out_ctr);
    knn_kernel<<<dim3(M_, B_), 256>>>(coords, out_ctr);
    mlp1_kernel<<<dim3(M_ / 2, B_), 256>>>(coords, W1, b1, out_ctr, out_temb);
    gn_fin_kernel<0><<<1, 512>>>();
    mlp2_kernel<<<dim3(M_ / 4, B_), 256>>>(W2, b2, g1, be1);
    gn_fin_kernel<1><<<1, 512>>>();
    out_kernel<<<(B_ * C2_ * M_) / 256, 256>>>(g2, be2, out_h);
}